// round 10
// baseline (speedup 1.0000x reference)
#include <cuda_runtime.h>
#include <math.h>

// FlexibleLogisticModel: f = sigmoid( sum_f w[f]*alpha[ord(f)]*monomial_f(x) ),
// all multiset monomials deg 0..4 in D=64 vars, lex CWR order. Never reads E.
//
// Phase A: g_OP[47840] = [pair products | triple products] (closed-form unrank,
// 1 elem/thread). Flag-relay grid barrier (no contended atomics; all 199 CTAs
// co-resident at <=2/SM). Phase B: element space e<->w[65+e] split into
// 16-element 16B-aligned chunks, ONE chunk per thread: 4x LDG.128 (w) + 16x LDG
// (OP) all issued before any FMA -> whole 3.26MB requested in ~1 latency.
// Segments (deg2 / deg3 / deg4-i1) give scale + OP delta; chunk spans <=2.
// deg-4 tail (i1>=52) per-lane closed-form; deg0/1 + first 15 elems on last
// warp. Per-block sums via g_bsum[] + flags; block 0 reduces, applies sigmoid,
// resets all state for graph replay.

#define D 64
#define NPAIR 2080
#define N3 45760
#define N4 766480
#define ETOT 814320            // 2080 + 45760 + 766480
#define ECUT 812955            // start of deg-4 i1=52 tail (ETOT - 1365)
#define NSEG 54                // deg2, deg3, deg4 i1=0..51
#define TPB 256
#define NBLKS 199              // ceil(50809/256); co-resident (cap 296)
#define NCHUNK 50809           // ceil((ECUT-15)/16)
#define TAILW 43               // warps covering 1365-elem tail

__device__ float    g_OP[47840];
__device__ double   g_bsum[NBLKS];
__device__ int      g_ready[NBLKS];
__device__ int      g_done[NBLKS];
__device__ int      g_go = 0;

__device__ __forceinline__ int C2i(int n) { return (n >= 2) ? (n * (n - 1)) / 2 : 0; }
__device__ __forceinline__ int C3i(int n) { return (n >= 3) ? (n * (n - 1) * (n - 2)) / 6 : 0; }
__device__ __forceinline__ int C4i(int n) { return (n >= 4) ? (n * (n - 1) * (n - 2) * (n - 3)) / 24 : 0; }

__device__ __forceinline__ int inv_C2(int v) {
    int n = (int)(0.5f * (1.0f + sqrtf(8.0f * (float)v + 1.0f)));
    n = (n > 3) ? n - 1 : 2;
    while (C2i(n) < v) n++;
    return n;
}
__device__ __forceinline__ int inv_C3(int v) {
    int n = (int)cbrtf(6.0f * (float)v);
    n = (n > 4) ? n - 2 : 3;
    while (C3i(n) < v) n++;
    return n;
}
__device__ __forceinline__ int inv_C4(int v) {
    int n = (int)sqrtf(sqrtf(24.0f * (float)v));
    n = (n > 5) ? n - 2 : 4;
    while (C4i(n) < v) n++;
    return n;
}

__global__ void __launch_bounds__(TPB)
poly_fused_kernel(const float* __restrict__ x,
                  const float* __restrict__ w,
                  const float* __restrict__ alphas,
                  float* __restrict__ out)
{
    __shared__ float  xs[D];
    __shared__ float  al[5];
    __shared__ int    bnd[NSEG + 1];
    __shared__ float  sscale[NSEG];
    __shared__ int    sdelta[NSEG];
    __shared__ double warp_sums[TPB / 32];

    const int tid  = threadIdx.x;
    const int bid  = blockIdx.x;
    const int lane = tid & 31;
    if (tid < D) xs[tid] = x[tid];
    if (tid < 5) al[tid] = alphas[tid];
    __syncthreads();

    // ---- segment tables ----
    if (tid == 0)      { bnd[0] = 0;     sscale[0] = al[2]; sdelta[0] = 0; }
    else if (tid == 1) { bnd[1] = NPAIR; sscale[1] = al[3]; sdelta[1] = 0; }
    else if (tid < NSEG) {
        const int i1 = tid - 2;
        bnd[tid]    = 47840 + (N4 - C4i(67 - i1));
        sscale[tid] = al[4] * xs[i1];
        sdelta[tid] = C4i(67 - i1) - C3i(66 - i1) - N4;
    } else if (tid == NSEG) {
        bnd[NSEG] = ECUT;
    }

    // ---- Phase A: build g_OP (1 element / thread, coalesced) ----
    const int gt = bid * TPB + tid;
    if (gt < NPAIR) {
        const int rem = NPAIR - gt;
        const int n = inv_C2(rem);
        const int i3 = 65 - n;
        const int i4 = i3 + (C2i(n) - rem);
        g_OP[gt] = xs[i3] * xs[i4];
    } else if (gt < 47840) {
        const int e3  = gt - NPAIR;
        const int rem = N3 - e3;
        const int b   = inv_C3(rem);          // b = 66 - j
        const int j   = 66 - b;
        const int k   = C3i(b) - rem;
        const int remp = C2i(65 - j) - k;
        const int n   = inv_C2(remp);
        const int i3  = 65 - n;
        const int i4  = i3 + (C2i(n) - remp);
        g_OP[gt] = xs[j] * xs[i3] * xs[i4];
    }

    // ---- flag-relay grid barrier (no contended atomics) ----
    __threadfence();
    __syncthreads();
    if (tid == 0) *(volatile int*)&g_ready[bid] = 1;
    if (bid == 0) {
        if (tid < NBLKS) { while (*(volatile int*)&g_ready[tid] == 0) { } }
        __syncthreads();
        if (tid == 0) { __threadfence(); *(volatile int*)&g_go = 1; }
    }
    if (tid == 0) {
        while (*(volatile int*)&g_go == 0) { }
        __threadfence();
    }
    __syncthreads();

    // ---- Phase B ----
    double local = 0.0;

    // chunks: thread gt owns e in [15+16*gt, +16) (last chunk = 12 elems)
    if (gt < NCHUNK) {
        const int e0  = 15 + (gt << 4);
        int len = ECUT - e0; if (len > 16) len = 16;

        int lo = 0, hi = NSEG - 1;
        #pragma unroll
        for (int it = 0; it < 6; ++it) {
            const int mid = (lo + hi + 1) >> 1;
            if (bnd[mid] <= e0) lo = mid; else hi = mid - 1;
        }
        const int s  = lo;
        int run1 = bnd[s + 1] - e0; if (run1 > len) run1 = len;
        const float sc1 = sscale[s];
        const int   dl1 = sdelta[s];
        const bool  cross = (run1 < len);
        const float sc2 = cross ? sscale[s + 1] : 0.0f;
        const int   dl2 = cross ? sdelta[s + 1] : dl1;

        // w loads: 4x LDG.128 (16B aligned: 4*(65+e0) = 320+64*gt)
        const float4* __restrict__ wv = (const float4*)(w + 65 + e0);
        const float4 v0 = wv[0];
        const float4 v1 = wv[1];
        const float4 v2 = wv[2];
        const float4 v3 = (len == 16) ? wv[3] : make_float4(0.f, 0.f, 0.f, 0.f);
        float wa[16] = { v0.x, v0.y, v0.z, v0.w,  v1.x, v1.y, v1.z, v1.w,
                         v2.x, v2.y, v2.z, v2.w,  v3.x, v3.y, v3.z, v3.w };

        // OP loads: 16 independent scalar LDGs (L1/L2-hot window)
        float o[16];
        #pragma unroll
        for (int k = 0; k < 16; ++k) {
            const int dl = (k < run1) ? dl1 : dl2;
            o[k] = (k < len) ? g_OP[e0 + k + dl] : 0.0f;
        }

        float acc1 = 0.f, acc2 = 0.f;
        #pragma unroll
        for (int k = 0; k < 16; ++k) {
            const float p = wa[k] * o[k];
            if (k < run1) acc1 += p; else acc2 += p;
        }
        local += (double)(sc1 * acc1) + (double)(sc2 * acc2);
    }

    const int gw = gt >> 5;

    // deg-4 tail (i1 >= 52): per-lane closed-form, warps 0..42
    if (gw < TAILW) {
        const int idx = ECUT + gw * 32 + lane;
        if (idx < ETOT) {
            const int e4  = idx - 47840;
            const int rem = N4 - e4;             // [1, 1365]
            const int a   = inv_C4(rem);         // a = 67 - i1
            const int i1  = 67 - a;
            const int k   = C4i(a) - rem;
            const int op  = NPAIR + (N3 - C3i(66 - i1)) + k;
            local += (double)(al[4] * xs[i1] * w[65 + idx] * g_OP[op]);
        }
    }

    // deg-0/1 + first 15 deg-2 elements: last warp (its chunks are out of range)
    if (gw == NBLKS * (TPB / 32) - 1) {
        float s = al[1] * (w[1 + lane] * xs[lane] + w[33 + lane] * xs[32 + lane]);
        if (lane == 0) s += al[0] * w[0];
        if (lane < 15) s += al[2] * w[65 + lane] * g_OP[lane];
        local += (double)s;
    }

    // ---- warp + block reduction ----
    #pragma unroll
    for (int o = 16; o > 0; o >>= 1)
        local += __shfl_down_sync(0xffffffffu, local, o);
    if (lane == 0) warp_sums[tid >> 5] = local;
    __syncthreads();

    if (tid == 0) {
        double bs = 0.0;
        #pragma unroll
        for (int i = 0; i < TPB / 32; i++) bs += warp_sums[i];
        g_bsum[bid] = bs;
        __threadfence();
        *(volatile int*)&g_done[bid] = 1;
    }

    // ---- block 0: wait all, reduce, finalize, reset ----
    if (bid == 0) {
        if (tid < NBLKS) { while (*(volatile int*)&g_done[tid] == 0) { } }
        __syncthreads();
        if (tid < 32) {
            __threadfence();
            double s = 0.0;
            for (int i = tid; i < NBLKS; i += 32) s += g_bsum[i];
            #pragma unroll
            for (int o = 16; o > 0; o >>= 1)
                s += __shfl_down_sync(0xffffffffu, s, o);
            for (int i = tid; i < NBLKS; i += 32) {   // reset flags for replay
                g_done[i] = 0;
                g_ready[i] = 0;
            }
            if (tid == 0) {
                g_go = 0;
                out[0] = (float)(1.0 / (1.0 + exp(-s)));
            }
        }
    }
}

extern "C" void kernel_launch(void* const* d_in, const int* in_sizes, int n_in,
                              void* d_out, int out_size)
{
    const float* x      = (const float*)d_in[0];
    const float* w      = (const float*)d_in[1];
    const float* alphas = (const float*)d_in[2];
    // d_in[3] = E (constant, NOT read), d_in[4] = ord_ids (NOT read)
    float* out = (float*)d_out;

    poly_fused_kernel<<<NBLKS, TPB>>>(x, w, alphas, out);
}